// round 2
// baseline (speedup 1.0000x reference)
#include <cuda_runtime.h>

#define B_     4
#define S_     16
#define T_     16
#define DIM_   512
#define HSP    32
#define WSP    32
#define HW_    1024
#define HEADS_ 8
#define DH_    64

// ---------------- scratch (no allocations allowed) ----------------
__device__ float g_qm[B_*S_*DIM_];
__device__ float g_km[B_*T_*DIM_];
__device__ float g_qp[B_*S_*DIM_];
__device__ float g_kp[B_*T_*DIM_];
__device__ float g_attn[B_*HEADS_*S_*T_];

// ---------------- kernel 1: spatial means of q and k ----------------
// one warp per (b, s|t, d) row of 1024 contiguous floats
__global__ void mean_kernel(const float* __restrict__ q, const float* __restrict__ k) {
    int w    = blockIdx.x * (blockDim.x >> 5) + (threadIdx.x >> 5);
    int lane = threadIdx.x & 31;
    const int NROW = B_*S_*DIM_;          // 32768 rows each
    const float* src;
    float* dst;
    int r;
    if (w < NROW) { src = q; dst = g_qm; r = w; }
    else          { src = k; dst = g_km; r = w - NROW; }
    const float4* p = (const float4*)(src + (size_t)r * HW_);
    float s = 0.f;
#pragma unroll
    for (int i = 0; i < 8; i++) {
        float4 v4 = p[lane + i*32];
        s += v4.x + v4.y + v4.z + v4.w;
    }
#pragma unroll
    for (int m = 16; m; m >>= 1) s += __shfl_xor_sync(0xffffffffu, s, m);
    if (lane == 0) dst[r] = s * (1.f/1024.f);
}

// ---------------- kernel 2: row @ W.T projections ----------------
// 128 blocks (64 qm rows then 64 km rows), 512 threads, W tiled into smem
__global__ void proj_kernel(const float* __restrict__ Wq, const float* __restrict__ Wk) {
    __shared__ float rowS[DIM_];
    __shared__ float Ws[DIM_*17];
    int rr  = blockIdx.x;
    int tid = threadIdx.x;
    const float* W; const float* in; float* out; float scale;
    if (rr < 64) { in = g_qm + rr*DIM_;      W = Wq; out = g_qp + rr*DIM_;      scale = 0.125f; } // dh^-0.5
    else         { in = g_km + (rr-64)*DIM_; W = Wk; out = g_kp + (rr-64)*DIM_; scale = 1.f;    }
    rowS[tid] = in[tid];
    float acc = 0.f;
    for (int e0 = 0; e0 < DIM_; e0 += 16) {
        __syncthreads();
#pragma unroll
        for (int i = 0; i < 16; i++) {
            int idx = tid + i*512;
            int d = idx >> 4, e = idx & 15;
            Ws[d*17 + e] = W[d*DIM_ + e0 + e];
        }
        __syncthreads();
#pragma unroll
        for (int e = 0; e < 16; e++)
            acc += rowS[e0 + e] * Ws[tid*17 + e];
    }
    out[tid] = acc * scale;
}

// ---------------- kernel 3: logits + softmax -> attn[b,h,s,t] ----------------
__global__ void attn_kernel() {
    int blk  = blockIdx.x;               // B*HEADS*S = 512
    int b    = blk >> 7;
    int h    = (blk >> 4) & 7;
    int s    = blk & 15;
    int lane = threadIdx.x;
    int t    = lane & 15;                // both warp halves duplicate work
    const float* qr = g_qp + (size_t)(b*16 + s)*DIM_ + h*DH_;
    const float* kr = g_kp + (size_t)(b*16 + t)*DIM_ + h*DH_;
    float lg = 0.f;
#pragma unroll
    for (int j = 0; j < DH_; j++) lg += qr[j] * kr[j];
    float mx = lg;
#pragma unroll
    for (int m = 8; m; m >>= 1) mx = fmaxf(mx, __shfl_xor_sync(0xffffffffu, mx, m));
    float e = __expf(lg - mx);
    float sm = e;
#pragma unroll
    for (int m = 8; m; m >>= 1) sm += __shfl_xor_sync(0xffffffffu, sm, m);
    if (lane < 16) g_attn[((b*8 + h)*16 + s)*16 + t] = e / sm;
}

// ---------------- kernel 4: fused Wv GEMM + attention mix + transpose write ----------------
// Tile: M = 256 rows (16 t x 16 p, p = 4x4 spatial square), N = 64 (one head), K = 512.
// f32x2 packed FMA inner loop (pairs along M; Wv pre-duplicated in smem).
#define KC 16
#define AP 260    // As row stride, floats
#define BP 68     // Bs2 row stride, u64 entries
#define CP 68     // Cs row stride, floats
#define SMEM4 (256*CP*4)   // 69632 bytes (unions As/Bs2)

extern __shared__ char smraw[];

__global__ __launch_bounds__(256, 2)
void main_kernel(const float* __restrict__ v, const float* __restrict__ Wv,
                 float* __restrict__ out) {
    float* As               = (float*)smraw;                        // [KC][AP]
    unsigned long long* Bs2 = (unsigned long long*)(smraw + KC*AP*4); // [KC][BP]
    float* Cs               = (float*)smraw;                        // [256][CP] (union, used after mainloop)

    int tid = threadIdx.x;
    int b   = blockIdx.z;
    int h   = blockIdx.y;
    int tx  = blockIdx.x;
    int h0  = (tx >> 3) * 4;            // spatial tile origin (h_i)
    int w0  = (tx & 7) * 4;             // spatial tile origin (w_i)
    int tm  = tid & 31, tn = tid >> 5;
    int m0  = tm * 8,   n0 = tn * 8;

    unsigned long long acc2[4][8];
#pragma unroll
    for (int i = 0; i < 4; i++)
#pragma unroll
        for (int j = 0; j < 8; j++) acc2[i][j] = 0ull;

    for (int kc = 0; kc < DIM_; kc += KC) {
        __syncthreads();
        // A: v[b, t, kc+kk, (h0+hh)*32 + w0 .. w0+3]  -> As[kk][t*16 + hh*4 + ww]
#pragma unroll
        for (int i = 0; i < 4; i++) {
            int idx = tid + i*256;                 // 1024 float4 loads
            int kk = idx >> 6, m4 = idx & 63;
            int t  = m4 >> 2,  hh = m4 & 3;
            const float4* src = (const float4*)(v +
                ((size_t)((b*16 + t)*512 + kc + kk))*1024 + (h0 + hh)*32 + w0);
            *((float4*)&As[kk*AP + t*16 + hh*4]) = *src;
        }
        // B: Wv[h*64+n, kc+kq..] duplicated into packed pairs
        {
            int n  = tid >> 2;
            int kq = (tid & 3) * 4;
            float4 w4 = *(const float4*)(Wv + (size_t)(h*64 + n)*512 + kc + kq);
            unsigned int u0 = __float_as_uint(w4.x), u1 = __float_as_uint(w4.y);
            unsigned int u2 = __float_as_uint(w4.z), u3 = __float_as_uint(w4.w);
            Bs2[(kq+0)*BP + n] = ((unsigned long long)u0 << 32) | u0;
            Bs2[(kq+1)*BP + n] = ((unsigned long long)u1 << 32) | u1;
            Bs2[(kq+2)*BP + n] = ((unsigned long long)u2 << 32) | u2;
            Bs2[(kq+3)*BP + n] = ((unsigned long long)u3 << 32) | u3;
        }
        __syncthreads();
#pragma unroll
        for (int kk = 0; kk < KC; kk++) {
            unsigned long long a2[4], bb[8];
            const ulonglong2* ap = (const ulonglong2*)&As[kk*AP + m0];
            ulonglong2 av0 = ap[0], av1 = ap[1];
            a2[0] = av0.x; a2[1] = av0.y; a2[2] = av1.x; a2[3] = av1.y;
            const ulonglong2* bp = (const ulonglong2*)&Bs2[kk*BP + n0];
            ulonglong2 bv0 = bp[0], bv1 = bp[1], bv2 = bp[2], bv3 = bp[3];
            bb[0] = bv0.x; bb[1] = bv0.y; bb[2] = bv1.x; bb[3] = bv1.y;
            bb[4] = bv2.x; bb[5] = bv2.y; bb[6] = bv3.x; bb[7] = bv3.y;
#pragma unroll
            for (int i = 0; i < 4; i++)
#pragma unroll
                for (int j = 0; j < 8; j++)
                    asm("fma.rn.f32x2 %0, %1, %2, %0;"
                        : "+l"(acc2[i][j]) : "l"(a2[i]), "l"(bb[j]));
        }
    }

    __syncthreads();   // mainloop done reading As/Bs2; Cs aliases them
    // unpack accumulators into Cs[m][n]
#pragma unroll
    for (int i = 0; i < 4; i++) {
        float lo[8], hi[8];
#pragma unroll
        for (int j = 0; j < 8; j++) {
            lo[j] = __uint_as_float((unsigned int)(acc2[i][j] & 0xffffffffull));
            hi[j] = __uint_as_float((unsigned int)(acc2[i][j] >> 32));
        }
        int mlo = m0 + 2*i, mhi = mlo + 1;
        *((float4*)&Cs[mlo*CP + n0    ]) = make_float4(lo[0], lo[1], lo[2], lo[3]);
        *((float4*)&Cs[mlo*CP + n0 + 4]) = make_float4(lo[4], lo[5], lo[6], lo[7]);
        *((float4*)&Cs[mhi*CP + n0    ]) = make_float4(hi[0], hi[1], hi[2], hi[3]);
        *((float4*)&Cs[mhi*CP + n0 + 4]) = make_float4(hi[4], hi[5], hi[6], hi[7]);
    }
    __syncthreads();

    // epilogue: out[s, p_out, n] = sum_t attn[b,h,s,t] * Cs[t*16+pp][n]
    int sn = tid >> 4;
    int pg = tid & 15;
    int hh = pg & 3, ww = pg >> 2;
    int pp = hh*4 + ww;                  // matches loader's m encoding

    float wt[16];
#pragma unroll
    for (int t = 0; t < 16; t++) wt[t] = g_attn[((b*8 + h)*16 + sn)*16 + t];

    float acc[64];
#pragma unroll
    for (int n = 0; n < 64; n++) acc[n] = 0.f;
#pragma unroll
    for (int t = 0; t < 16; t++) {
        float w = wt[t];
        const float* crow = &Cs[(t*16 + pp)*CP];
#pragma unroll
        for (int n4 = 0; n4 < 16; n4++) {
            float4 c = *((const float4*)&crow[n4*4]);
            acc[n4*4+0] += w * c.x;
            acc[n4*4+1] += w * c.y;
            acc[n4*4+2] += w * c.z;
            acc[n4*4+3] += w * c.w;
        }
    }
    // output spatial index is the transpose of input spatial index:
    // pin = (h0+hh)*32 + (w0+ww)  ->  p_out = (w0+ww)*32 + (h0+hh)
    float* op = out + ((size_t)((b*16 + sn)*512 + h*64))*1024 + (w0 + ww)*32 + h0 + hh;
#pragma unroll
    for (int n = 0; n < 64; n++) op[(size_t)n*1024] = acc[n];
}

// ---------------- launcher ----------------
extern "C" void kernel_launch(void* const* d_in, const int* in_sizes, int n_in,
                              void* d_out, int out_size) {
    const float* q  = (const float*)d_in[0];
    const float* k  = (const float*)d_in[1];
    const float* v  = (const float*)d_in[2];
    const float* Wq = (const float*)d_in[3];
    const float* Wk = (const float*)d_in[4];
    const float* Wv = (const float*)d_in[5];
    float* out = (float*)d_out;

    cudaFuncSetAttribute(main_kernel, cudaFuncAttributeMaxDynamicSharedMemorySize, SMEM4);

    mean_kernel<<<8192, 256>>>(q, k);      // 65536 rows, 8 warps/block
    proj_kernel<<<128, 512>>>(Wq, Wk);
    attn_kernel<<<512, 32>>>();
    dim3 g4(64, HEADS_, B_);
    main_kernel<<<g4, 256, SMEM4>>>(v, Wv, out);
}

// round 3
// speedup vs baseline: 1.0001x; 1.0001x over previous
#include <cuda_runtime.h>

#define B_     4
#define S_     16
#define T_     16
#define DIM_   512
#define HSP    32
#define WSP    32
#define HW_    1024
#define HEADS_ 8
#define DH_    64

// ---------------- scratch (no allocations allowed) ----------------
__device__ float g_qm[B_*S_*DIM_];
__device__ float g_km[B_*T_*DIM_];
__device__ float g_qp[B_*S_*DIM_];
__device__ float g_kp[B_*T_*DIM_];
__device__ float g_attn[B_*HEADS_*S_*T_];

// ---------------- kernel 1: spatial means of q and k ----------------
// one warp per (b, s|t, d) row of 1024 contiguous floats
__global__ void mean_kernel(const float* __restrict__ q, const float* __restrict__ k) {
    int w    = blockIdx.x * (blockDim.x >> 5) + (threadIdx.x >> 5);
    int lane = threadIdx.x & 31;
    const int NROW = B_*S_*DIM_;          // 32768 rows each
    const float* src;
    float* dst;
    int r;
    if (w < NROW) { src = q; dst = g_qm; r = w; }
    else          { src = k; dst = g_km; r = w - NROW; }
    const float4* p = (const float4*)(src + (size_t)r * HW_);
    float s = 0.f;
#pragma unroll
    for (int i = 0; i < 8; i++) {
        float4 v4 = p[lane + i*32];
        s += v4.x + v4.y + v4.z + v4.w;
    }
#pragma unroll
    for (int m = 16; m; m >>= 1) s += __shfl_xor_sync(0xffffffffu, s, m);
    if (lane == 0) dst[r] = s * (1.f/1024.f);
}

// ---------------- kernel 2: row @ W.T projections ----------------
// 128 blocks (64 qm rows then 64 km rows), 512 threads, W tiled into smem
__global__ void proj_kernel(const float* __restrict__ Wq, const float* __restrict__ Wk) {
    __shared__ float rowS[DIM_];
    __shared__ float Ws[DIM_*17];
    int rr  = blockIdx.x;
    int tid = threadIdx.x;
    const float* W; const float* in; float* out; float scale;
    if (rr < 64) { in = g_qm + rr*DIM_;      W = Wq; out = g_qp + rr*DIM_;      scale = 0.125f; } // dh^-0.5
    else         { in = g_km + (rr-64)*DIM_; W = Wk; out = g_kp + (rr-64)*DIM_; scale = 1.f;    }
    rowS[tid] = in[tid];
    float acc = 0.f;
    for (int e0 = 0; e0 < DIM_; e0 += 16) {
        __syncthreads();
#pragma unroll
        for (int i = 0; i < 16; i++) {
            int idx = tid + i*512;
            int d = idx >> 4, e = idx & 15;
            Ws[d*17 + e] = W[d*DIM_ + e0 + e];
        }
        __syncthreads();
#pragma unroll
        for (int e = 0; e < 16; e++)
            acc += rowS[e0 + e] * Ws[tid*17 + e];
    }
    out[tid] = acc * scale;
}

// ---------------- kernel 3: logits + softmax -> attn[b,h,s,t] ----------------
__global__ void attn_kernel() {
    int blk  = blockIdx.x;               // B*HEADS*S = 512
    int b    = blk >> 7;
    int h    = (blk >> 4) & 7;
    int s    = blk & 15;
    int lane = threadIdx.x;
    int t    = lane & 15;                // both warp halves duplicate work
    const float* qr = g_qp + (size_t)(b*16 + s)*DIM_ + h*DH_;
    const float* kr = g_kp + (size_t)(b*16 + t)*DIM_ + h*DH_;
    float lg = 0.f;
#pragma unroll
    for (int j = 0; j < DH_; j++) lg += qr[j] * kr[j];
    float mx = lg;
#pragma unroll
    for (int m = 8; m; m >>= 1) mx = fmaxf(mx, __shfl_xor_sync(0xffffffffu, mx, m));
    float e = __expf(lg - mx);
    float sm = e;
#pragma unroll
    for (int m = 8; m; m >>= 1) sm += __shfl_xor_sync(0xffffffffu, sm, m);
    if (lane < 16) g_attn[((b*8 + h)*16 + s)*16 + t] = e / sm;
}

// ---------------- kernel 4: fused Wv GEMM + attention mix + transpose write ----------------
// Tile: M = 256 rows (16 t x 16 p, p = 4x4 spatial square), N = 64 (one head), K = 512.
// f32x2 packed FMA inner loop (pairs along M; Wv pre-duplicated in smem).
#define KC 16
#define AP 260    // As row stride, floats
#define BP 68     // Bs2 row stride, u64 entries
#define CP 68     // Cs row stride, floats
#define SMEM4 (256*CP*4)   // 69632 bytes (unions As/Bs2)

extern __shared__ char smraw[];

__global__ __launch_bounds__(256, 2)
void main_kernel(const float* __restrict__ v, const float* __restrict__ Wv,
                 float* __restrict__ out) {
    float* As               = (float*)smraw;                        // [KC][AP]
    unsigned long long* Bs2 = (unsigned long long*)(smraw + KC*AP*4); // [KC][BP]
    float* Cs               = (float*)smraw;                        // [256][CP] (union, used after mainloop)

    int tid = threadIdx.x;
    int b   = blockIdx.z;
    int h   = blockIdx.y;
    int tx  = blockIdx.x;
    int h0  = (tx >> 3) * 4;            // spatial tile origin (h_i)
    int w0  = (tx & 7) * 4;             // spatial tile origin (w_i)
    int tm  = tid & 31, tn = tid >> 5;
    int m0  = tm * 8,   n0 = tn * 8;

    unsigned long long acc2[4][8];
#pragma unroll
    for (int i = 0; i < 4; i++)
#pragma unroll
        for (int j = 0; j < 8; j++) acc2[i][j] = 0ull;

    for (int kc = 0; kc < DIM_; kc += KC) {
        __syncthreads();
        // A: v[b, t, kc+kk, (h0+hh)*32 + w0 .. w0+3]  -> As[kk][t*16 + hh*4 + ww]
#pragma unroll
        for (int i = 0; i < 4; i++) {
            int idx = tid + i*256;                 // 1024 float4 loads
            int kk = idx >> 6, m4 = idx & 63;
            int t  = m4 >> 2,  hh = m4 & 3;
            const float4* src = (const float4*)(v +
                ((size_t)((b*16 + t)*512 + kc + kk))*1024 + (h0 + hh)*32 + w0);
            *((float4*)&As[kk*AP + t*16 + hh*4]) = *src;
        }
        // B: Wv[h*64+n, kc+kq..] duplicated into packed pairs
        {
            int n  = tid >> 2;
            int kq = (tid & 3) * 4;
            float4 w4 = *(const float4*)(Wv + (size_t)(h*64 + n)*512 + kc + kq);
            unsigned int u0 = __float_as_uint(w4.x), u1 = __float_as_uint(w4.y);
            unsigned int u2 = __float_as_uint(w4.z), u3 = __float_as_uint(w4.w);
            Bs2[(kq+0)*BP + n] = ((unsigned long long)u0 << 32) | u0;
            Bs2[(kq+1)*BP + n] = ((unsigned long long)u1 << 32) | u1;
            Bs2[(kq+2)*BP + n] = ((unsigned long long)u2 << 32) | u2;
            Bs2[(kq+3)*BP + n] = ((unsigned long long)u3 << 32) | u3;
        }
        __syncthreads();
#pragma unroll
        for (int kk = 0; kk < KC; kk++) {
            unsigned long long a2[4], bb[8];
            const ulonglong2* ap = (const ulonglong2*)&As[kk*AP + m0];
            ulonglong2 av0 = ap[0], av1 = ap[1];
            a2[0] = av0.x; a2[1] = av0.y; a2[2] = av1.x; a2[3] = av1.y;
            const ulonglong2* bp = (const ulonglong2*)&Bs2[kk*BP + n0];
            ulonglong2 bv0 = bp[0], bv1 = bp[1], bv2 = bp[2], bv3 = bp[3];
            bb[0] = bv0.x; bb[1] = bv0.y; bb[2] = bv1.x; bb[3] = bv1.y;
            bb[4] = bv2.x; bb[5] = bv2.y; bb[6] = bv3.x; bb[7] = bv3.y;
#pragma unroll
            for (int i = 0; i < 4; i++)
#pragma unroll
                for (int j = 0; j < 8; j++)
                    asm("fma.rn.f32x2 %0, %1, %2, %0;"
                        : "+l"(acc2[i][j]) : "l"(a2[i]), "l"(bb[j]));
        }
    }

    __syncthreads();   // mainloop done reading As/Bs2; Cs aliases them
    // unpack accumulators into Cs[m][n]
#pragma unroll
    for (int i = 0; i < 4; i++) {
        float lo[8], hi[8];
#pragma unroll
        for (int j = 0; j < 8; j++) {
            lo[j] = __uint_as_float((unsigned int)(acc2[i][j] & 0xffffffffull));
            hi[j] = __uint_as_float((unsigned int)(acc2[i][j] >> 32));
        }
        int mlo = m0 + 2*i, mhi = mlo + 1;
        *((float4*)&Cs[mlo*CP + n0    ]) = make_float4(lo[0], lo[1], lo[2], lo[3]);
        *((float4*)&Cs[mlo*CP + n0 + 4]) = make_float4(lo[4], lo[5], lo[6], lo[7]);
        *((float4*)&Cs[mhi*CP + n0    ]) = make_float4(hi[0], hi[1], hi[2], hi[3]);
        *((float4*)&Cs[mhi*CP + n0 + 4]) = make_float4(hi[4], hi[5], hi[6], hi[7]);
    }
    __syncthreads();

    // epilogue: out[s, p_out, n] = sum_t attn[b,h,s,t] * Cs[t*16+pp][n]
    int sn = tid >> 4;
    int pg = tid & 15;
    int hh = pg & 3, ww = pg >> 2;
    int pp = hh*4 + ww;                  // matches loader's m encoding

    float wt[16];
#pragma unroll
    for (int t = 0; t < 16; t++) wt[t] = g_attn[((b*8 + h)*16 + sn)*16 + t];

    float acc[64];
#pragma unroll
    for (int n = 0; n < 64; n++) acc[n] = 0.f;
#pragma unroll
    for (int t = 0; t < 16; t++) {
        float w = wt[t];
        const float* crow = &Cs[(t*16 + pp)*CP];
#pragma unroll
        for (int n4 = 0; n4 < 16; n4++) {
            float4 c = *((const float4*)&crow[n4*4]);
            acc[n4*4+0] += w * c.x;
            acc[n4*4+1] += w * c.y;
            acc[n4*4+2] += w * c.z;
            acc[n4*4+3] += w * c.w;
        }
    }
    // output spatial index is the transpose of input spatial index:
    // pin = (h0+hh)*32 + (w0+ww)  ->  p_out = (w0+ww)*32 + (h0+hh)
    float* op = out + ((size_t)((b*16 + sn)*512 + h*64))*1024 + (w0 + ww)*32 + h0 + hh;
#pragma unroll
    for (int n = 0; n < 64; n++) op[(size_t)n*1024] = acc[n];
}

// ---------------- launcher ----------------
extern "C" void kernel_launch(void* const* d_in, const int* in_sizes, int n_in,
                              void* d_out, int out_size) {
    const float* q  = (const float*)d_in[0];
    const float* k  = (const float*)d_in[1];
    const float* v  = (const float*)d_in[2];
    const float* Wq = (const float*)d_in[3];
    const float* Wk = (const float*)d_in[4];
    const float* Wv = (const float*)d_in[5];
    float* out = (float*)d_out;

    cudaFuncSetAttribute(main_kernel, cudaFuncAttributeMaxDynamicSharedMemorySize, SMEM4);

    mean_kernel<<<8192, 256>>>(q, k);      // 65536 rows, 8 warps/block
    proj_kernel<<<128, 512>>>(Wq, Wk);
    attn_kernel<<<512, 32>>>();
    dim3 g4(64, HEADS_, B_);
    main_kernel<<<g4, 256, SMEM4>>>(v, Wv, out);
}